// round 17
// baseline (speedup 1.0000x reference)
#include <cuda_runtime.h>

// Additive (Bahdanau) attention, fully fused, round 17 — flash-style merge.
// tanh(q+k) = 1 - 2/(1 + Eq*Ek); 4-way batched rcp (upd4).
// Per 128-s chunk: scores -> exp -> small E tile in SMEM -> barrier -> AV
// accumulation with V streamed straight from L2 (register prefetch, no SMEM V).
// No SCO score buffer, no separate softmax pass. K: single SMEM buffer,
// refilled (LDG->STS) during the AV half of each chunk.

#define B_  2
#define L_  512
#define S_  512
#define H_  8
#define E_  32
#define D_  64
#define TL  16
#define SC  128
#define NCH (S_/SC)      // 4
#define NT  256
#define KSTRIDE 36       // padded K row stride (floats), conflict-free LDS.128
#define ESTR 132         // E tile row stride (floats)
#define EBUF (TL*ESTR)   // 2112
#define WSN 56           // WS: [0..31]=m(perm)/rowsum scratch, [32]=sumW

typedef unsigned long long u64;

__device__ __forceinline__ float rcp_(float x) {
    float r; asm("rcp.approx.f32 %0, %1;" : "=f"(r) : "f"(x)); return r;
}
__device__ __forceinline__ float ex2_(float x) {
    float r; asm("ex2.approx.f32 %0, %1;" : "=f"(r) : "f"(x)); return r;
}
__device__ __forceinline__ u64 bcast2(float a) {
    u64 r; asm("mov.b64 %0, {%1, %1};" : "=l"(r) : "f"(a)); return r;
}
__device__ __forceinline__ float2 unpack2(u64 p) {
    float2 f; asm("mov.b64 {%0, %1}, %2;" : "=f"(f.x), "=f"(f.y) : "l"(p)); return f;
}
__device__ __forceinline__ void fma2(u64& acc, u64 a, u64 b) {
    asm("fma.rn.f32x2 %0, %1, %2, %0;" : "+l"(acc) : "l"(a), "l"(b));
}
// acc += sum_{i=0..3} m_i/d_i with d_i = 1 + t_i*k_i (one rcp per 4 elements).
// Swizzled pair layout: lo-u64 = {e0,e2}, hi-u64 = {e1,e3}.
__device__ __forceinline__ void upd4(u64 tlo, u64 thi, u64 klo, u64 khi,
                                     u64 mP, u64 mQ, u64 one2, float& acc) {
    asm("{\n\t"
        ".reg .b64 dP, dQ, Dp, Np;\n\t"
        ".reg .f32 D01, D23, N01, N23, Nn, Dd, r;\n\t"
        "fma.rn.f32x2 dP, %1, %3, %7;\n\t"
        "fma.rn.f32x2 dQ, %2, %4, %7;\n\t"
        "mul.rn.f32x2 Dp, dP, dQ;\n\t"
        "mul.rn.f32x2 Np, %5, dQ;\n\t"
        "fma.rn.f32x2 Np, %6, dP, Np;\n\t"
        "mov.b64 {D01, D23}, Dp;\n\t"
        "mov.b64 {N01, N23}, Np;\n\t"
        "mul.f32 Nn, N01, D23;\n\t"
        "fma.rn.f32 Nn, N23, D01, Nn;\n\t"
        "mul.f32 Dd, D01, D23;\n\t"
        "rcp.approx.f32 r, Dd;\n\t"
        "fma.rn.f32 %0, Nn, r, %0;\n\t"
        "}"
        : "+f"(acc)
        : "l"(tlo), "l"(thi), "l"(klo), "l"(khi), "l"(mP), "l"(mQ), "l"(one2));
}
#define C2Q 2.8853900817779268f   // 2*log2(e)
#define L2E 1.4426950408889634f   // log2(e)
__device__ __forceinline__ float4 exp2q4s(float4 x) {   // swizzled (x,z,y,w)
    return make_float4(ex2_(x.x * C2Q), ex2_(x.z * C2Q),
                       ex2_(x.y * C2Q), ex2_(x.w * C2Q));
}

__global__ void __launch_bounds__(NT, 4)
addattn_kernel(const float* __restrict__ q,
               const float* __restrict__ k,
               const float* __restrict__ val,
               const float* __restrict__ v,
               const float* __restrict__ am,
               const float* __restrict__ kl,
               float* __restrict__ out)
{
    extern __shared__ float sm[];
    float* TQ = sm;                  // 512 (Eq tile, swizzled)
    float* WS = TQ + TL * E_;        // 56
    float* EB = WS + WSN;            // 2112 (exp-score tile, one chunk)
    float* KB = EB + EBUF;           // 4608 (K chunk / final O-partial scratch)

    const int t  = threadIdx.x;
    const int bh = blockIdx.y;
    const int b  = bh >> 3, h = bh & 7;
    const int l0 = blockIdx.x * TL;

    const float* amp = am + (size_t)l0 * S_;
    const float* klb = kl + b * S_;
    const float* kbase = k   + ((size_t)b * S_ * H_ + h) * E_;
    const float* vbase = val + ((size_t)b * S_ * H_ + h) * D_;

    // ---- phase 0: m (swizzled), sumW, Eq tile; K chunk 0 -> KB ----
    if (t < E_) {
        float w = v[t];
        int pos = (t & ~3) | ((t & 1) << 1) | ((t >> 1) & 1);   // swap e1<->e2
        WS[pos] = -2.0f * w;
        #pragma unroll
        for (int o = 16; o; o >>= 1) w += __shfl_xor_sync(0xffffffffu, w, o);
        if (t == 0) WS[32] = w;
    }
    if (t < TL * E_ / 4) {
        int l = t >> 3, e4 = t & 7;
        float4 qv = ((const float4*)(q + ((size_t)(b * L_ + l0 + l) * H_ + h) * E_))[e4];
        ((float4*)TQ)[t] = exp2q4s(qv);
    }
    #pragma unroll
    for (int j = 0; j < 4; ++j) {
        int i = j * NT + t, r = i >> 3, e4 = i & 7;
        float4 kv = ((const float4*)(kbase + (size_t)r * H_ * E_))[e4];
        ((float4*)(KB + r * KSTRIDE))[e4] = exp2q4s(kv);
    }
    __syncthreads();
    const float sumW = WS[32];

    // score roles
    const int si = t & 63;
    const int lg = t >> 6;
    const int lb = lg * 4;
    const u64 one2 = 0x3F8000003F800000ULL;
    const ulonglong2* wv  = (const ulonglong2*)WS;
    const ulonglong2* tqp = (const ulonglong2*)(TQ + lb * E_);
    float rs0 = 0.f, rs1 = 0.f, rs2 = 0.f, rs3 = 0.f;

    // AV roles
    const int dg = t & 15;           // d float4 group
    const int rb = (t >> 4) & 3;     // row block (4 rows)
    const int sh = t >> 6;           // s quarter (32 s per chunk)
    u64 ac[4][2] = {{0,0},{0,0},{0,0},{0,0}};

    #pragma unroll 1
    for (int c = 0; c < NCH; ++c) {
        // ---- score half: 8 scores/thread -> exp -> EB; rowsums in regs ----
        const int sg0 = c * SC + si, sg1 = sg0 + 64;
        const float base0 = sumW + klb[sg0];
        const float base1 = sumW + klb[sg1];
        float a00 = base0 + amp[(lb+0)*S_+sg0];
        float a01 = base0 + amp[(lb+1)*S_+sg0];
        float a02 = base0 + amp[(lb+2)*S_+sg0];
        float a03 = base0 + amp[(lb+3)*S_+sg0];
        float a10 = base1 + amp[(lb+0)*S_+sg1];
        float a11 = base1 + amp[(lb+1)*S_+sg1];
        float a12 = base1 + amp[(lb+2)*S_+sg1];
        float a13 = base1 + amp[(lb+3)*S_+sg1];

        const ulonglong2* kp0 = (const ulonglong2*)(KB + si * KSTRIDE);
        const ulonglong2* kp1 = (const ulonglong2*)(KB + (si + 64) * KSTRIDE);
        #pragma unroll
        for (int e4 = 0; e4 < E_/4; ++e4) {
            const ulonglong2 M  = wv[e4];
            const ulonglong2 K0 = kp0[e4];
            const ulonglong2 K1 = kp1[e4];
            const ulonglong2 T0 = tqp[e4];
            const ulonglong2 T1 = tqp[8  + e4];
            const ulonglong2 T2 = tqp[16 + e4];
            const ulonglong2 T3 = tqp[24 + e4];
            upd4(T0.x, T0.y, K0.x, K0.y, M.x, M.y, one2, a00);
            upd4(T1.x, T1.y, K0.x, K0.y, M.x, M.y, one2, a01);
            upd4(T2.x, T2.y, K0.x, K0.y, M.x, M.y, one2, a02);
            upd4(T3.x, T3.y, K0.x, K0.y, M.x, M.y, one2, a03);
            upd4(T0.x, T0.y, K1.x, K1.y, M.x, M.y, one2, a10);
            upd4(T1.x, T1.y, K1.x, K1.y, M.x, M.y, one2, a11);
            upd4(T2.x, T2.y, K1.x, K1.y, M.x, M.y, one2, a12);
            upd4(T3.x, T3.y, K1.x, K1.y, M.x, M.y, one2, a13);
        }
        float e;
        e = ex2_(a00 * L2E); EB[(lb+0)*ESTR + si     ] = e; rs0 += e;
        e = ex2_(a01 * L2E); EB[(lb+1)*ESTR + si     ] = e; rs1 += e;
        e = ex2_(a02 * L2E); EB[(lb+2)*ESTR + si     ] = e; rs2 += e;
        e = ex2_(a03 * L2E); EB[(lb+3)*ESTR + si     ] = e; rs3 += e;
        e = ex2_(a10 * L2E); EB[(lb+0)*ESTR + si + 64] = e; rs0 += e;
        e = ex2_(a11 * L2E); EB[(lb+1)*ESTR + si + 64] = e; rs1 += e;
        e = ex2_(a12 * L2E); EB[(lb+2)*ESTR + si + 64] = e; rs2 += e;
        e = ex2_(a13 * L2E); EB[(lb+3)*ESTR + si + 64] = e; rs3 += e;
        __syncthreads();     // EB ready; KB free for refill

        // ---- AV half: O += E_chunk x V_chunk (V from L2) + K refill ----
        if (c + 1 < NCH) {   // LDG->STS next K chunk (overlaps AV compute)
            #pragma unroll
            for (int j = 0; j < 4; ++j) {
                int i = j * NT + t, r = i >> 3, e4 = i & 7;
                float4 kv = ((const float4*)(kbase + (size_t)((c+1)*SC + r) * H_ * E_))[e4];
                ((float4*)(KB + r * KSTRIDE))[e4] = exp2q4s(kv);
            }
        }
        const float* Erow = EB + rb * 4 * ESTR + sh * 32;
        const float* vsg  = vbase + (size_t)(c * SC + sh * 32) * H_ * D_ + dg * 4;
        ulonglong2 V0, V1, V2, V3;
        V0 = *(const ulonglong2*)(vsg + 0 * H_ * D_);
        V1 = *(const ulonglong2*)(vsg + 1 * H_ * D_);
        V2 = *(const ulonglong2*)(vsg + 2 * H_ * D_);
        V3 = *(const ulonglong2*)(vsg + 3 * H_ * D_);
        #pragma unroll
        for (int sb = 0; sb < 8; ++sb) {
            const float4 A0 = *(const float4*)(Erow + 0*ESTR + sb*4);
            const float4 A1 = *(const float4*)(Erow + 1*ESTR + sb*4);
            const float4 A2 = *(const float4*)(Erow + 2*ESTR + sb*4);
            const float4 A3 = *(const float4*)(Erow + 3*ESTR + sb*4);
            ulonglong2 W0 = V0, W1 = V1, W2 = V2, W3 = V3;
            if (sb < 7) {    // prefetch next 4 s rows
                const float* nv = vsg + (size_t)(sb*4 + 4) * H_ * D_;
                V0 = *(const ulonglong2*)(nv + 0 * H_ * D_);
                V1 = *(const ulonglong2*)(nv + 1 * H_ * D_);
                V2 = *(const ulonglong2*)(nv + 2 * H_ * D_);
                V3 = *(const ulonglong2*)(nv + 3 * H_ * D_);
            }
            u64 b2;
            b2 = bcast2(A0.x); fma2(ac[0][0], b2, W0.x); fma2(ac[0][1], b2, W0.y);
            b2 = bcast2(A0.y); fma2(ac[0][0], b2, W1.x); fma2(ac[0][1], b2, W1.y);
            b2 = bcast2(A0.z); fma2(ac[0][0], b2, W2.x); fma2(ac[0][1], b2, W2.y);
            b2 = bcast2(A0.w); fma2(ac[0][0], b2, W3.x); fma2(ac[0][1], b2, W3.y);
            b2 = bcast2(A1.x); fma2(ac[1][0], b2, W0.x); fma2(ac[1][1], b2, W0.y);
            b2 = bcast2(A1.y); fma2(ac[1][0], b2, W1.x); fma2(ac[1][1], b2, W1.y);
            b2 = bcast2(A1.z); fma2(ac[1][0], b2, W2.x); fma2(ac[1][1], b2, W2.y);
            b2 = bcast2(A1.w); fma2(ac[1][0], b2, W3.x); fma2(ac[1][1], b2, W3.y);
            b2 = bcast2(A2.x); fma2(ac[2][0], b2, W0.x); fma2(ac[2][1], b2, W0.y);
            b2 = bcast2(A2.y); fma2(ac[2][0], b2, W1.x); fma2(ac[2][1], b2, W1.y);
            b2 = bcast2(A2.z); fma2(ac[2][0], b2, W2.x); fma2(ac[2][1], b2, W2.y);
            b2 = bcast2(A2.w); fma2(ac[2][0], b2, W3.x); fma2(ac[2][1], b2, W3.y);
            b2 = bcast2(A3.x); fma2(ac[3][0], b2, W0.x); fma2(ac[3][1], b2, W0.y);
            b2 = bcast2(A3.y); fma2(ac[3][0], b2, W1.x); fma2(ac[3][1], b2, W1.y);
            b2 = bcast2(A3.z); fma2(ac[3][0], b2, W2.x); fma2(ac[3][1], b2, W2.y);
            b2 = bcast2(A3.w); fma2(ac[3][0], b2, W3.x); fma2(ac[3][1], b2, W3.y);
        }
        __syncthreads();     // KB refilled + EB reusable for next chunk
    }

    // ---- rowsum reduction -> WS[0..31] (m values dead) ----
    const int warp = t >> 5, lane = t & 31;
    #pragma unroll
    for (int o = 16; o; o >>= 1) {
        rs0 += __shfl_xor_sync(0xffffffffu, rs0, o);
        rs1 += __shfl_xor_sync(0xffffffffu, rs1, o);
        rs2 += __shfl_xor_sync(0xffffffffu, rs2, o);
        rs3 += __shfl_xor_sync(0xffffffffu, rs3, o);
    }
    if (lane == 0) {
        WS[warp*4 + 0] = rs0;
        WS[warp*4 + 1] = rs1;
        WS[warp*4 + 2] = rs2;
        WS[warp*4 + 3] = rs3;
    }

    // ---- O-partial reduction over sh via KB (free), scale, write ----
    #pragma unroll
    for (int i = 0; i < 4; ++i) {
        float2 p01 = unpack2(ac[i][0]), p23 = unpack2(ac[i][1]);
        ((float4*)KB)[(sh * 16 + rb * 4 + i) * 16 + dg] =
            make_float4(p01.x, p01.y, p23.x, p23.y);
    }
    __syncthreads();
    {
        const int row = t >> 4, dgr = t & 15;
        const int j = row >> 2, i = row & 3;
        const float inv = rcp_(WS[8*j + i] + WS[8*j + 4 + i]);
        const float4* vp = (const float4*)KB;
        float4 r0 = vp[(  0 + row)*16 + dgr];
        float4 r1 = vp[( 16 + row)*16 + dgr];
        float4 r2 = vp[( 32 + row)*16 + dgr];
        float4 r3 = vp[( 48 + row)*16 + dgr];
        float4 o4 = make_float4((r0.x+r1.x+r2.x+r3.x)*inv, (r0.y+r1.y+r2.y+r3.y)*inv,
                                (r0.z+r1.z+r2.z+r3.z)*inv, (r0.w+r1.w+r2.w+r3.w)*inv);
        *reinterpret_cast<float4*>(out + ((size_t)(b*L_ + l0 + row)*H_ + h)*D_ + dgr*4) = o4;
    }
}

// SMEM: 512 + 56 + 2112 + 4608 = 7288 floats = 29152 bytes (4 CTAs/SM, reg-limited)
static const int SMEM_BYTES = (TL*E_ + WSN + EBUF + SC*KSTRIDE) * (int)sizeof(float);

extern "C" void kernel_launch(void* const* d_in, const int* in_sizes, int n_in,
                              void* d_out, int out_size)
{
    const float* q   = (const float*)d_in[0];
    const float* k   = (const float*)d_in[1];
    const float* val = (const float*)d_in[2];
    const float* v   = (const float*)d_in[3];
    const float* am  = (const float*)d_in[4];
    const float* kl  = (const float*)d_in[5];
    float* out = (float*)d_out;

    cudaFuncSetAttribute(addattn_kernel,
                         cudaFuncAttributeMaxDynamicSharedMemorySize, SMEM_BYTES);
    dim3 grid(L_ / TL, B_ * H_);
    addattn_kernel<<<grid, NT, SMEM_BYTES>>>(q, k, val, v, am, kl, out);
}